// round 12
// baseline (speedup 1.0000x reference)
#include <cuda_runtime.h>
#include <cuda_fp16.h>
#include <cstdint>

// ---------------- problem constants ----------------
#define BATCH   2048
#define NATOM   96
#define NIN     128
#define NHID    64
#define SHIFTC  0.6931471805599453f

// fp32 staging tile in SMEM: 96 rows x (512B data + 32B pad) -> LDS.64 fragment
// gather is conflict-free per 16-lane phase (bank pair = 4*qr + qc, all distinct).
#define ROWB   544
#define TILEB  (NATOM * ROWB)          // 52224 B
#define SMEMB  (TILEB + 32)            // + reduction slots

// ---------------- precomputed W1 fp16 image (B-fragment layout) ----------------
// uint2 index = (nt*8 + kt)*32 + lane ; .x = b0 (k pair, khalf 0), .y = b1 (khalf 1)
__device__ __align__(16) uint2 g_wh[2048];   // 16 KB, L1/L2-resident

__global__ void prep_w_kernel(const float* __restrict__ W1) {
    int idx = blockIdx.x * blockDim.x + threadIdx.x;
    if (idx >= NIN * NHID) return;
    int k = idx >> 6;          // 0..127
    int n = idx & 63;          // 0..63
    __half h = __float2half_rn(W1[idx]);
    int nt = n >> 3, g = n & 7;
    int kt = k >> 4, kl = k & 15;
    int tg = (kl >> 1) & 3, br = kl >> 3, odd = kl & 1;
    uint32_t off = (uint32_t)((((nt * 8 + kt) * 32 + (g * 4 + tg)) * 8) + br * 4 + odd * 2);
    *reinterpret_cast<__half*>(reinterpret_cast<unsigned char*>(g_wh) + off) = h;
}

// ---------------- device helpers ----------------
__device__ __forceinline__ void mma_f16(float* c, const uint32_t* a, const uint32_t* b) {
    asm volatile(
        "mma.sync.aligned.m16n8k16.row.col.f32.f16.f16.f32 "
        "{%0,%1,%2,%3}, {%4,%5,%6,%7}, {%8,%9}, {%0,%1,%2,%3};"
        : "+f"(c[0]), "+f"(c[1]), "+f"(c[2]), "+f"(c[3])
        : "r"(a[0]), "r"(a[1]), "r"(a[2]), "r"(a[3]), "r"(b[0]), "r"(b[1]));
}

__device__ __forceinline__ float ssp(float z) {
    // shifted softplus, numerically stable
    return fmaxf(z, 0.f) + __logf(1.f + __expf(-fabsf(z))) - SHIFTC;
}

__device__ __forceinline__ uint32_t cvt2h(float x, float y) {
    __half2 h = __floats2half2_rn(x, y);
    return *reinterpret_cast<uint32_t*>(&h);
}

__device__ __forceinline__ float2 lds64(uint32_t addr) {
    float2 v;
    asm volatile("ld.shared.v2.f32 {%0,%1}, [%2];" : "=f"(v.x), "=f"(v.y) : "r"(addr));
    return v;
}

// ---------------- main fused kernel: one CTA (3 warps) per batch sample ----------------
// R11 post-mortem: DRAM pinned at ~45% across four rounds = request-concurrency
// ceiling (fill MLP register-bounded at 8 LDGs/warp).  cp.async.cg stages the whole
// 48KB rep tile GMEM->SMEM fp32 with NO register cost and unbounded depth (32
// 16B copies per thread, one commit group).  A fragments come from SMEM via
// conflict-free LDS.64 + cvt; fp16 tile + ldmatrix + register fill chain all gone.
__global__ void __launch_bounds__(96, 4)
atomwise_kernel(const float* __restrict__ rep,
                const int*   __restrict__ atomic_numbers,
                const float* __restrict__ atom_mask,
                const float* __restrict__ b1,
                const float* __restrict__ W2,
                const float* __restrict__ b2,
                const float* __restrict__ atomref,
                const float* __restrict__ mean,
                const float* __restrict__ stddev,
                float*       __restrict__ out) {
    extern __shared__ __align__(16) unsigned char smem[];
    float* red = reinterpret_cast<float*>(smem + TILEB);

    const int tid  = threadIdx.x;
    const int w    = tid >> 5;          // warp 0..2
    const int lane = tid & 31;
    const int b    = blockIdx.x;

    const int qr = lane >> 2;           // 0..7 (row group)
    const int qc = lane & 3;            // 0..3 (col pair)
    const int r0 = w * 32 + qr;         // rows r0, r0+8 (m-tile 0); r0+16, r0+24 (m-tile 1)

    const float*   xb = rep + (size_t)b * (NATOM * NIN);
    const uint32_t sb = (uint32_t)__cvta_generic_to_shared(smem);

    // ---- async fill: 3072 16B chunks (96 rows x 32), all in flight at once ----
    {
        const char* gsrc = reinterpret_cast<const char*>(xb);
        #pragma unroll
        for (int i = 0; i < 32; i++) {
            int idx = i * 96 + tid;            // warp-consecutive lanes = one full row
            int r = idx >> 5, c = idx & 31;
            uint32_t dst = sb + (uint32_t)(r * ROWB + c * 16);
            asm volatile("cp.async.cg.shared.global [%0], [%1], 16;"
                         :: "r"(dst), "l"(gsrc + (r * 512 + c * 16)));
        }
        asm volatile("cp.async.commit_group;" ::: "memory");
    }

    float acc[2][8][4];
    #pragma unroll
    for (int m = 0; m < 2; m++)
        #pragma unroll
        for (int nt = 0; nt < 8; nt++)
            #pragma unroll
            for (int r = 0; r < 4; r++) acc[m][nt][r] = 0.f;

    asm volatile("cp.async.wait_group 0;" ::: "memory");
    __syncthreads();

    // SMEM row bases for this thread's fragment rows
    const uint32_t sR0 = sb + (uint32_t)((r0     ) * ROWB) + (uint32_t)(qc * 8);
    const uint32_t sR1 = sb + (uint32_t)((r0 +  8) * ROWB) + (uint32_t)(qc * 8);
    const uint32_t sR2 = sb + (uint32_t)((r0 + 16) * ROWB) + (uint32_t)(qc * 8);
    const uint32_t sR3 = sb + (uint32_t)((r0 + 24) * ROWB) + (uint32_t)(qc * 8);

    #pragma unroll
    for (int kt = 0; kt < 8; kt++) {
        const uint32_t cb = (uint32_t)(kt * 64);
        float2 f0 = lds64(sR0 + cb);
        float2 f1 = lds64(sR1 + cb);
        float2 f2 = lds64(sR0 + cb + 32);
        float2 f3 = lds64(sR1 + cb + 32);
        float2 g0 = lds64(sR2 + cb);
        float2 g1 = lds64(sR3 + cb);
        float2 g2 = lds64(sR2 + cb + 32);
        float2 g3 = lds64(sR3 + cb + 32);

        uint32_t a0[4], a1[4];
        a0[0] = cvt2h(f0.x, f0.y);
        a0[1] = cvt2h(f1.x, f1.y);
        a0[2] = cvt2h(f2.x, f2.y);
        a0[3] = cvt2h(f3.x, f3.y);
        a1[0] = cvt2h(g0.x, g0.y);
        a1[1] = cvt2h(g1.x, g1.y);
        a1[2] = cvt2h(g2.x, g2.y);
        a1[3] = cvt2h(g3.x, g3.y);

        #pragma unroll
        for (int nt = 0; nt < 8; nt++) {
            uint2 bb = __ldg(&g_wh[(nt * 8 + kt) * 32 + lane]);  // L1-hit after warmup
            mma_f16(acc[0][nt], a0, &bb.x);
            mma_f16(acc[1][nt], a1, &bb.x);
        }
    }

    // ---- epilogue: bias + ssp + W2 dot, quad shuffle-reduce ----
    float sum0 = 0.f, sum1 = 0.f, sum2 = 0.f, sum3 = 0.f;  // rows r0, r0+8, r0+16, r0+24
    const int tg2 = qc * 2;
    #pragma unroll
    for (int nt = 0; nt < 8; nt++) {
        int c0 = nt * 8 + tg2;
        float2 b1v = __ldg(reinterpret_cast<const float2*>(b1 + c0));
        float2 w2v = __ldg(reinterpret_cast<const float2*>(W2 + c0));
        sum0 = fmaf(ssp(acc[0][nt][0] + b1v.x), w2v.x, sum0);
        sum0 = fmaf(ssp(acc[0][nt][1] + b1v.y), w2v.y, sum0);
        sum1 = fmaf(ssp(acc[0][nt][2] + b1v.x), w2v.x, sum1);
        sum1 = fmaf(ssp(acc[0][nt][3] + b1v.y), w2v.y, sum1);
        sum2 = fmaf(ssp(acc[1][nt][0] + b1v.x), w2v.x, sum2);
        sum2 = fmaf(ssp(acc[1][nt][1] + b1v.y), w2v.y, sum2);
        sum3 = fmaf(ssp(acc[1][nt][2] + b1v.x), w2v.x, sum3);
        sum3 = fmaf(ssp(acc[1][nt][3] + b1v.y), w2v.y, sum3);
    }
    // reduce over the 4 lanes of each quad (cols)
    sum0 += __shfl_xor_sync(0xffffffffu, sum0, 1);
    sum0 += __shfl_xor_sync(0xffffffffu, sum0, 2);
    sum1 += __shfl_xor_sync(0xffffffffu, sum1, 1);
    sum1 += __shfl_xor_sync(0xffffffffu, sum1, 2);
    sum2 += __shfl_xor_sync(0xffffffffu, sum2, 1);
    sum2 += __shfl_xor_sync(0xffffffffu, sum2, 2);
    sum3 += __shfl_xor_sync(0xffffffffu, sum3, 1);
    sum3 += __shfl_xor_sync(0xffffffffu, sum3, 2);

    // per-row finish on quad leaders, then warp-sum (deterministic)
    float contrib = 0.f;
    if (qc == 0) {
        float scB2 = b2[0], scMean = mean[0], scStd = stddev[0];
        float s[4] = {sum0, sum1, sum2, sum3};
        float tot = 0.f;
        #pragma unroll
        for (int m = 0; m < 4; m++) {
            int row = r0 + m * 8;
            int g = b * NATOM + row;
            float v = (s[m] + scB2) * scStd + scMean;
            v += atomref[atomic_numbers[g]];
            v *= atom_mask[g];
            tot += v;
        }
        contrib = tot;
    }
    // nonzero only at lanes ≡ 0 (mod 4): stages 4, 8, 16 suffice
    contrib += __shfl_xor_sync(0xffffffffu, contrib, 4);
    contrib += __shfl_xor_sync(0xffffffffu, contrib, 8);
    contrib += __shfl_xor_sync(0xffffffffu, contrib, 16);

    if (lane == 0) red[w] = contrib;
    __syncthreads();
    if (tid == 0) out[b] = red[0] + red[1] + red[2];
}

// ---------------- host launch ----------------
extern "C" void kernel_launch(void* const* d_in, const int* in_sizes, int n_in,
                              void* d_out, int out_size) {
    const float* rep   = (const float*)d_in[0];
    const int*   zn    = (const int*)  d_in[1];
    const float* mask  = (const float*)d_in[2];
    const float* W1    = (const float*)d_in[3];
    const float* b1    = (const float*)d_in[4];
    const float* W2    = (const float*)d_in[5];
    const float* b2    = (const float*)d_in[6];
    const float* aref  = (const float*)d_in[7];
    const float* mean  = (const float*)d_in[8];
    const float* stdd  = (const float*)d_in[9];
    float* out = (float*)d_out;

    cudaFuncSetAttribute(atomwise_kernel, cudaFuncAttributeMaxDynamicSharedMemorySize, SMEMB);

    prep_w_kernel<<<32, 256>>>(W1);
    atomwise_kernel<<<BATCH, 96, SMEMB>>>(rep, zn, mask, b1, W2, b2, aref, mean, stdd, out);
}